// round 6
// baseline (speedup 1.0000x reference)
#include <cuda_runtime.h>
#include <cuda_bf16.h>
#include <stdint.h>

// Segment-max of a per-row scalar projection.
//   r[n] = dot(feats[n,:32], W) + b ;  out[p] = max(0, max_{idx[n]==p} r[n])
//
// Memory-bound: 512MB feats read once. One thread per row, 8x LDG.128,
// no-return atomicMax on int bits (valid since all committed values >= 0).

__device__ int g_idx_is32;   // 1 if idx stored as int32, 0 if int64 (low-word stride 2)

// ---------------------------------------------------------------------------
// Kernel 1: zero output (bit pattern 0 == 0.0f) and clear detect flag
// ---------------------------------------------------------------------------
__global__ void init_kernel(float* __restrict__ out, int p) {
    int i = blockIdx.x * blockDim.x + threadIdx.x;
    if (i < p) out[i] = 0.0f;
    if (i == 0) g_idx_is32 = 0;
}

// ---------------------------------------------------------------------------
// Kernel 2: detect idx dtype, reading ONLY the first nrows 32-bit words —
// in-bounds for BOTH layouts (int32 buffer = nrows words; int64 = 2*nrows).
// If idx is int64 (LE, values < 2^17), odd words in [1, nrows) are high
// halves = 0. If int32, odd words are idx values: zero w.p. 1e-5 each, so
// 1024 spread samples all-zero => int64, effectively no misdetect risk.
// ---------------------------------------------------------------------------
__global__ void detect_kernel(const int* __restrict__ idx_words, int nrows) {
    int i = blockIdx.x * blockDim.x + threadIdx.x;     // i in [0, 1024)
    if (i >= 1024) return;
    long long stride = (long long)nrows / 2048; if (stride < 1) stride = 1;
    long long k = ((long long)i * stride * 2) | 1;      // odd word index
    if (k < nrows) {                                    // << in-bounds either way
        if (idx_words[k] != 0) atomicOr(&g_idx_is32, 1);
    }
}

// ---------------------------------------------------------------------------
// Kernel 3: main fused projection + segment max
// ---------------------------------------------------------------------------
__global__ __launch_bounds__(256) void segmax_kernel(
    const float4* __restrict__ feats,   // [N, 8] float4  (= [N,32] float)
    const float*  __restrict__ W,       // [32]
    const float*  __restrict__ b,       // [1]
    const int*    __restrict__ idx_w,   // idx as 32-bit words
    float*        __restrict__ out,     // [P]
    int nrows)
{
    int i = blockIdx.x * blockDim.x + threadIdx.x;
    if (i >= nrows) return;

    // W into registers (L1 broadcast hit for all threads)
    const float4* w4 = (const float4*)W;
    float4 w0 = w4[0], w1 = w4[1], w2 = w4[2], w3 = w4[3];
    float4 w4_ = w4[4], w5 = w4[5], w6 = w4[6], w7 = w4[7];

    const float4* row = feats + (size_t)i * 8;
    float4 f0 = row[0], f1 = row[1], f2 = row[2], f3 = row[3];
    float4 f4 = row[4], f5 = row[5], f6 = row[6], f7 = row[7];

    // 4 independent accumulators for ILP
    float a0 = f0.x * w0.x, a1 = f0.y * w0.y, a2 = f0.z * w0.z, a3 = f0.w * w0.w;
    a0 = fmaf(f1.x, w1.x, a0); a1 = fmaf(f1.y, w1.y, a1);
    a2 = fmaf(f1.z, w1.z, a2); a3 = fmaf(f1.w, w1.w, a3);
    a0 = fmaf(f2.x, w2.x, a0); a1 = fmaf(f2.y, w2.y, a1);
    a2 = fmaf(f2.z, w2.z, a2); a3 = fmaf(f2.w, w2.w, a3);
    a0 = fmaf(f3.x, w3.x, a0); a1 = fmaf(f3.y, w3.y, a1);
    a2 = fmaf(f3.z, w3.z, a2); a3 = fmaf(f3.w, w3.w, a3);
    a0 = fmaf(f4.x, w4_.x, a0); a1 = fmaf(f4.y, w4_.y, a1);
    a2 = fmaf(f4.z, w4_.z, a2); a3 = fmaf(f4.w, w4_.w, a3);
    a0 = fmaf(f5.x, w5.x, a0); a1 = fmaf(f5.y, w5.y, a1);
    a2 = fmaf(f5.z, w5.z, a2); a3 = fmaf(f5.w, w5.w, a3);
    a0 = fmaf(f6.x, w6.x, a0); a1 = fmaf(f6.y, w6.y, a1);
    a2 = fmaf(f6.z, w6.z, a2); a3 = fmaf(f6.w, w6.w, a3);
    a0 = fmaf(f7.x, w7.x, a0); a1 = fmaf(f7.y, w7.y, a1);
    a2 = fmaf(f7.z, w7.z, a2); a3 = fmaf(f7.w, w7.w, a3);

    float r = (a0 + a1) + (a2 + a3) + b[0];

    if (r > 0.0f) {
        int seg = g_idx_is32 ? idx_w[i] : idx_w[2 * (size_t)i];  // int64 low word
        atomicMax((int*)out + seg, __float_as_int(r));           // -> REDG (no return)
    }
}

// ---------------------------------------------------------------------------
extern "C" void kernel_launch(void* const* d_in, const int* in_sizes, int n_in,
                              void* d_out, int out_size)
{
    const float4* feats = (const float4*)d_in[0];
    const float*  W     = (const float*) d_in[1];
    const float*  b     = (const float*) d_in[2];
    const int*    idx_w = (const int*)   d_in[3];

    int nrows = in_sizes[0] / 32;   // N rows (feats element count / F) — dtype-proof
    int P     = out_size;           // 100,000

    float* out = (float*)d_out;

    int tb = 256;
    init_kernel<<<(P + tb - 1) / tb, tb>>>(out, P);
    detect_kernel<<<4, 256>>>(idx_w, nrows);
    segmax_kernel<<<(nrows + tb - 1) / tb, tb>>>(feats, W, b, idx_w, out, nrows);
}

// round 7
// speedup vs baseline: 1.8140x; 1.8140x over previous
#include <cuda_runtime.h>
#include <cuda_bf16.h>
#include <stdint.h>

// Segment-max of per-row scalar projection, warp-cooperative coalesced loads.
//   r[n] = dot(feats[n,:32], W) + b ;  out[p] = max(0, max_{idx[n]==p} r[n])
//
// R6 finding: one-thread-per-row LDG.128 = 32 lines/instr -> L1tex wavefront
// bound (~3.75 TB/s). Fix: 8 lanes/row, 512B contiguous per LDG.128 (4 lines),
// shfl_xor reduction over 8-lane groups. 32 rows per warp, MLP=8.

__device__ int g_idx_is32;   // 1 if idx stored as int32, 0 if int64

__global__ void init_kernel(float* __restrict__ out, int p) {
    int i = blockIdx.x * blockDim.x + threadIdx.x;
    if (i < p) out[i] = 0.0f;
    if (i == 0) g_idx_is32 = 0;
}

// Detect idx dtype, reading ONLY first nrows words (in-bounds for both
// layouts). int64 (values < 2^17): odd words are zero high-halves. int32:
// odd words are idx values, ~never all zero across 1024 spread samples.
__global__ void detect_kernel(const int* __restrict__ idx_words, int nrows) {
    int i = blockIdx.x * blockDim.x + threadIdx.x;
    if (i >= 1024) return;
    long long stride = (long long)nrows / 2048; if (stride < 1) stride = 1;
    long long k = ((long long)i * stride * 2) | 1;
    if (k < nrows) {
        if (idx_words[k] != 0) atomicOr(&g_idx_is32, 1);
    }
}

__global__ __launch_bounds__(256) void segmax_kernel(
    const float4* __restrict__ feats,   // [N,8] float4
    const float*  __restrict__ W,       // [32]
    const float*  __restrict__ b,       // [1]
    const int*    __restrict__ idx_w,   // idx as 32-bit words
    float*        __restrict__ out,     // [P]
    int nrows)
{
    int gwarp = (blockIdx.x * blockDim.x + threadIdx.x) >> 5;
    int lane  = threadIdx.x & 31;
    long long rowBase = (long long)gwarp * 32;
    if (rowBase >= nrows) return;

    const bool  is32 = (g_idx_is32 != 0);
    const float bias = b[0];
    const float4 wv  = ((const float4*)W)[lane & 7];   // lane's weight chunk

    // Coalesced idx prefetch: lane l holds seg of row rowBase+l
    long long ir = rowBase + lane;
    if (ir >= nrows) ir = nrows - 1;
    int myseg = is32 ? idx_w[ir] : idx_w[2 * ir];

    const float4* base4 = feats + rowBase * 8;

    if (rowBase + 32 <= nrows) {
        // ---- fast path: 8 fully-coalesced LDG.128, front-batched (MLP=8)
        float4 v[8];
#pragma unroll
        for (int k = 0; k < 8; k++) v[k] = base4[k * 32 + lane];

#pragma unroll
        for (int k = 0; k < 8; k++) {
            float s = fmaf(v[k].x, wv.x,
                      fmaf(v[k].y, wv.y,
                      fmaf(v[k].z, wv.z, v[k].w * wv.w)));
            s += __shfl_xor_sync(0xffffffffu, s, 1);
            s += __shfl_xor_sync(0xffffffffu, s, 2);
            s += __shfl_xor_sync(0xffffffffu, s, 4);
            // row handled by this 8-lane group in pass k:
            int rsel = k * 4 + (lane >> 3);            // 0..31 within warp
            int seg  = __shfl_sync(0xffffffffu, myseg, rsel);
            float r  = s + bias;
            if ((lane & 7) == 0 && r > 0.0f)
                atomicMax((int*)out + seg, __float_as_int(r));
        }
    } else {
        // ---- tail path (rare): guard each row
        for (int k = 0; k < 8; k++) {
            long long row = rowBase + k * 4 + (lane >> 3);
            float4 v = make_float4(0.f, 0.f, 0.f, 0.f);
            if (row < nrows) v = base4[k * 32 + lane];
            float s = fmaf(v.x, wv.x, fmaf(v.y, wv.y, fmaf(v.z, wv.z, v.w * wv.w)));
            s += __shfl_xor_sync(0xffffffffu, s, 1);
            s += __shfl_xor_sync(0xffffffffu, s, 2);
            s += __shfl_xor_sync(0xffffffffu, s, 4);
            int rsel = k * 4 + (lane >> 3);
            int seg  = __shfl_sync(0xffffffffu, myseg, rsel);
            float r  = s + bias;
            if ((lane & 7) == 0 && r > 0.0f && row < nrows)
                atomicMax((int*)out + seg, __float_as_int(r));
        }
    }
}

extern "C" void kernel_launch(void* const* d_in, const int* in_sizes, int n_in,
                              void* d_out, int out_size)
{
    const float4* feats = (const float4*)d_in[0];
    const float*  W     = (const float*) d_in[1];
    const float*  b     = (const float*) d_in[2];
    const int*    idx_w = (const int*)   d_in[3];

    int nrows = in_sizes[0] / 32;   // N rows (feats element count / F)
    int P     = out_size;           // 100,000

    float* out = (float*)d_out;

    int tb = 256;
    init_kernel<<<(P + tb - 1) / tb, tb>>>(out, P);
    detect_kernel<<<4, 256>>>(idx_w, nrows);
    // one warp per 32 rows, 8 warps per block => 256 rows per block
    int blocks = (int)(((long long)nrows + 255) / 256);
    segmax_kernel<<<blocks, tb>>>(feats, W, b, idx_w, out, nrows);
}

// round 8
// speedup vs baseline: 1.8198x; 1.0032x over previous
#include <cuda_runtime.h>
#include <cuda_bf16.h>
#include <stdint.h>

// Segment-max of per-row scalar projection, warp-cooperative coalesced loads.
//   r[n] = dot(feats[n,:32], W) + b ;  out[p] = max(0, max_{idx[n]==p} r[n])
//
// R7 state: segmax streams at ~7.0 TB/s (LTS cap). Residual = launch overhead.
// This round: fuse init (zero out) + idx-dtype detect into one kernel.

__device__ int g_idx_is32;   // 1 if idx stored as int32, 0 if int64

// ---------------------------------------------------------------------------
// Kernel 1 (fused): zero output (float4 stores) + detect idx dtype.
// Detection reads ONLY the first nrows 32-bit words (in-bounds for both
// layouts: int32 buffer = nrows words, int64 = 2*nrows). int64 with values
// < 2^17 => odd words are zero high-halves; int32 => odd words are idx
// values, ~never all zero across 1024 spread samples.
// ---------------------------------------------------------------------------
__global__ void init_detect_kernel(float4* __restrict__ out4, int p4,
                                   const int* __restrict__ idx_words, int nrows,
                                   int nzb /* # zeroing blocks */)
{
    if ((int)blockIdx.x < nzb) {
        int i = blockIdx.x * blockDim.x + threadIdx.x;
        if (i < p4) out4[i] = make_float4(0.f, 0.f, 0.f, 0.f);
        if (i == 0) g_idx_is32 = 0;   // visible before detect block? ensure below
    } else {
        // detect block: spin-free — flag cleared by static init is not allowed
        // across graph replays, so clear it HERE first via thread 0 of this
        // block, then sample. Ordering within the block via __syncthreads.
        if (threadIdx.x == 0) g_idx_is32 = 0;
        __syncthreads();
        int i = threadIdx.x + 256 * 0;          // 1024 samples via 4 passes
        #pragma unroll
        for (int pass = 0; pass < 4; pass++, i += 256) {
            long long stride = (long long)nrows / 2048; if (stride < 1) stride = 1;
            long long k = ((long long)i * stride * 2) | 1;   // odd word index
            if (k < nrows && idx_words[k] != 0) { atomicOr(&g_idx_is32, 1); break; }
        }
    }
}

// ---------------------------------------------------------------------------
// Kernel 2: main fused projection + segment max (unchanged 7 TB/s path)
// ---------------------------------------------------------------------------
__global__ __launch_bounds__(256) void segmax_kernel(
    const float4* __restrict__ feats,   // [N,8] float4
    const float*  __restrict__ W,       // [32]
    const float*  __restrict__ b,       // [1]
    const int*    __restrict__ idx_w,   // idx as 32-bit words
    float*        __restrict__ out,     // [P]
    int nrows)
{
    int gwarp = (blockIdx.x * blockDim.x + threadIdx.x) >> 5;
    int lane  = threadIdx.x & 31;
    long long rowBase = (long long)gwarp * 32;
    if (rowBase >= nrows) return;

    const bool  is32 = (g_idx_is32 != 0);
    const float bias = b[0];
    const float4 wv  = ((const float4*)W)[lane & 7];   // lane's weight chunk

    // Coalesced idx prefetch: lane l holds seg of row rowBase+l
    long long ir = rowBase + lane;
    if (ir >= nrows) ir = nrows - 1;
    int myseg = is32 ? idx_w[ir] : idx_w[2 * ir];

    const float4* base4 = feats + rowBase * 8;

    if (rowBase + 32 <= nrows) {
        // ---- fast path: 8 fully-coalesced LDG.128, front-batched (MLP=8)
        float4 v[8];
#pragma unroll
        for (int k = 0; k < 8; k++) v[k] = base4[k * 32 + lane];

#pragma unroll
        for (int k = 0; k < 8; k++) {
            float s = fmaf(v[k].x, wv.x,
                      fmaf(v[k].y, wv.y,
                      fmaf(v[k].z, wv.z, v[k].w * wv.w)));
            s += __shfl_xor_sync(0xffffffffu, s, 1);
            s += __shfl_xor_sync(0xffffffffu, s, 2);
            s += __shfl_xor_sync(0xffffffffu, s, 4);
            int rsel = k * 4 + (lane >> 3);            // row within warp
            int seg  = __shfl_sync(0xffffffffu, myseg, rsel);
            float r  = s + bias;
            if ((lane & 7) == 0 && r > 0.0f)
                atomicMax((int*)out + seg, __float_as_int(r));
        }
    } else {
        // ---- tail path (rare): guard each row
        for (int k = 0; k < 8; k++) {
            long long row = rowBase + k * 4 + (lane >> 3);
            float4 v = make_float4(0.f, 0.f, 0.f, 0.f);
            if (row < nrows) v = base4[k * 32 + lane];
            float s = fmaf(v.x, wv.x, fmaf(v.y, wv.y, fmaf(v.z, wv.z, v.w * wv.w)));
            s += __shfl_xor_sync(0xffffffffu, s, 1);
            s += __shfl_xor_sync(0xffffffffu, s, 2);
            s += __shfl_xor_sync(0xffffffffu, s, 4);
            int rsel = k * 4 + (lane >> 3);
            int seg  = __shfl_sync(0xffffffffu, myseg, rsel);
            float r  = s + bias;
            if ((lane & 7) == 0 && r > 0.0f && row < nrows)
                atomicMax((int*)out + seg, __float_as_int(r));
        }
    }
}

// ---------------------------------------------------------------------------
extern "C" void kernel_launch(void* const* d_in, const int* in_sizes, int n_in,
                              void* d_out, int out_size)
{
    const float4* feats = (const float4*)d_in[0];
    const float*  W     = (const float*) d_in[1];
    const float*  b     = (const float*) d_in[2];
    const int*    idx_w = (const int*)   d_in[3];

    int nrows = in_sizes[0] / 32;   // N rows (feats element count / F)
    int P     = out_size;           // 100,000 (multiple of 4)

    float* out = (float*)d_out;

    int p4  = P / 4;                              // float4 count (25,000)
    int nzb = (p4 + 255) / 256;                   // zeroing blocks
    init_detect_kernel<<<nzb + 1, 256>>>((float4*)out, p4, idx_w, nrows, nzb);

    // one warp per 32 rows, 8 warps per block => 256 rows per block
    int blocks = (int)(((long long)nrows + 255) / 256);
    segmax_kernel<<<blocks, 256>>>(feats, W, b, idx_w, out, nrows);
}